// round 6
// baseline (speedup 1.0000x reference)
#include <cuda_runtime.h>

#define CIN     512
#define COUT    32
#define HW      56
#define PLANE   3136
#define HPAD    58
#define WPAD    64
#define CHPAD   (HPAD * WPAD)        // 3712 floats per padded channel
#define KC      8
#define NCHUNK  (CIN / KC)           // 64
#define TH      8
#define TW      28
#define XROWS   10
#define XCOLS   32
#define NTHREADS 224
#define XELEMS  (KC * XROWS * XCOLS) // 2560 floats
#define WELEMS  (KC * 9 * COUT)      // 2304 floats
#define XF4     (XELEMS / 4)         // 640 16B ops
#define WF4     (WELEMS / 4)         // 576 16B ops

// scratch (device globals per harness rules)
__device__ float g_xpad[32 * CIN * CHPAD];       // BN+ReLU'd, zero-padded halo
__device__ float g_wt[CIN * 9 * COUT];           // weights as [c][kh][kw][oc]

// ---------------- Kernel 1: BN+ReLU into padded layout ----------------
__global__ __launch_bounds__(256) void bn_relu_pad(
    const float* __restrict__ x, const float* __restrict__ gamma,
    const float* __restrict__ beta, const float* __restrict__ rmean,
    const float* __restrict__ rvar)
{
    __shared__ float sp[PLANE];
    const int id  = blockIdx.x;          // plane id = n*512 + c
    const int c   = id & (CIN - 1);
    const int tid = threadIdx.x;

    float inv = rsqrtf(__ldg(&rvar[c]) + 1e-5f);
    float sc  = __ldg(&gamma[c]) * inv;
    float sh  = fmaf(-__ldg(&rmean[c]), sc, __ldg(&beta[c]));

    const float4* src = (const float4*)(x + (size_t)id * PLANE);
    for (int i = tid; i < PLANE / 4; i += 256) {
        float4 v = src[i];
        v.x = fmaxf(fmaf(v.x, sc, sh), 0.0f);
        v.y = fmaxf(fmaf(v.y, sc, sh), 0.0f);
        v.z = fmaxf(fmaf(v.z, sc, sh), 0.0f);
        v.w = fmaxf(fmaf(v.w, sc, sh), 0.0f);
        ((float4*)sp)[i] = v;
    }
    __syncthreads();

    float4* dst = (float4*)(g_xpad + (size_t)id * CHPAD);
    for (int i = tid; i < HPAD * (WPAD / 4); i += 256) {
        int hp = i >> 4, v4 = i & 15;
        float4 o = make_float4(0.f, 0.f, 0.f, 0.f);
        if (hp >= 1 && hp <= HW) {
            const float* row = sp + (hp - 1) * HW;
            int pc = v4 * 4;
            float t[4];
#pragma unroll
            for (int j = 0; j < 4; j++) {
                int p = pc + j;
                t[j] = (p >= 1 && p <= HW) ? row[p - 1] : 0.0f;
            }
            o = make_float4(t[0], t[1], t[2], t[3]);
        }
        dst[i] = o;
    }
}

// ---------------- Kernel 2: weight transpose [oc][c][k] -> [c][k][oc] ----------------
__global__ __launch_bounds__(256) void wt_transpose(const float* __restrict__ cw)
{
    int idx = blockIdx.x * 256 + threadIdx.x;
    if (idx >= CIN * 9 * COUT) return;
    int ck = idx >> 5, oc = idx & 31;
    g_wt[idx] = cw[oc * (CIN * 9) + ck];
}

// ---------------- Kernel 3: conv 3x3, 16B cp.async double-buffered, FFMA2 ----------------
__device__ __forceinline__ unsigned smem_u32(const void* p) {
    return (unsigned)__cvta_generic_to_shared(p);
}

__global__ __launch_bounds__(NTHREADS, 4)
void conv3x3_async(float* __restrict__ out)
{
    __shared__ __align__(16) float s_x[2][XELEMS];   // 20.5 KB
    __shared__ __align__(16) float s_w[2][WELEMS];   // 18.4 KB

    const int tid = threadIdx.x;
    const int n   = blockIdx.z;
    const int h0  = blockIdx.y * TH;
    const int w0  = blockIdx.x * TW;

    const int ocg = tid & 3;           // quads share x float4 (LDS broadcast)
    const int pix = tid >> 2;
    const int ty  = pix / 7;
    const int tx4 = (pix % 7) * 4;

    // chunk-invariant staging offsets (3 slots, float units / byte units)
    unsigned xsrc[3], xdst[3];
#pragma unroll
    for (int t = 0; t < 3; t++) {
        int s = tid + t * NTHREADS;            // < XF4 except slot2 when tid>=192
        int c = s / 80, rem = s % 80;
        int r = rem / 8, v = rem % 8;
        xsrc[t] = c * CHPAD + (h0 + r) * WPAD + w0 + v * 4;
        xdst[t] = ((c * XROWS + r) * XCOLS + v * 4) * 4u;
    }

    const float* xplane = g_xpad + (size_t)n * CIN * CHPAD;
    unsigned sxb[2] = { smem_u32(s_x[0]), smem_u32(s_x[1]) };
    unsigned swb[2] = { smem_u32(s_w[0]), smem_u32(s_w[1]) };

    unsigned long long acc[4][4];
#pragma unroll
    for (int j = 0; j < 4; j++)
#pragma unroll
        for (int q = 0; q < 4; q++) acc[j][q] = 0ull;

    // ---- staging lambda ----
    auto stage = [&](int k, int b) {
        const float* xb = xplane + (size_t)k * KC * CHPAD;
        const float* wb = g_wt + k * WELEMS;
#pragma unroll
        for (int t = 0; t < 3; t++) {
            if (t < 2 || tid < XF4 - 2 * NTHREADS) {
                asm volatile("cp.async.cg.shared.global [%0], [%1], 16;\n"
                             :: "r"(sxb[b] + xdst[t]), "l"(xb + xsrc[t]));
            }
        }
#pragma unroll
        for (int t = 0; t < 3; t++) {
            int s = tid + t * NTHREADS;
            if (t < 2 || tid < WF4 - 2 * NTHREADS) {
                asm volatile("cp.async.cg.shared.global [%0], [%1], 16;\n"
                             :: "r"(swb[b] + (unsigned)s * 16u), "l"(wb + s * 4));
            }
        }
        asm volatile("cp.async.commit_group;\n" ::: "memory");
    };

    stage(0, 0);
    stage(1, 1);

#pragma unroll 1
    for (int k = 0; k < NCHUNK; k++) {
        if (k < NCHUNK - 1) asm volatile("cp.async.wait_group 1;\n" ::: "memory");
        else                asm volatile("cp.async.wait_group 0;\n" ::: "memory");
        __syncthreads();
        const int b = k & 1;
        const float* sx = s_x[b];
        const float* sw = s_w[b];
#pragma unroll
        for (int c = 0; c < KC; c++) {
#pragma unroll
            for (int kh = 0; kh < 3; kh++) {
                const float* xr = sx + ((c * XROWS + ty + kh) * XCOLS + tx4);
                float4 a  = *(const float4*)xr;
                float2 b2 = *(const float2*)(xr + 4);
                float xv[6] = {a.x, a.y, a.z, a.w, b2.x, b2.y};
                unsigned long long xx[6];
#pragma unroll
                for (int t = 0; t < 6; t++) {
                    unsigned u = __float_as_uint(xv[t]);
                    asm("mov.b64 %0, {%1, %1};" : "=l"(xx[t]) : "r"(u));
                }
#pragma unroll
                for (int kw = 0; kw < 3; kw++) {
                    const unsigned long long* wp = (const unsigned long long*)
                        (sw + ((c * 3 + kh) * 3 + kw) * COUT + ocg * 8);
                    unsigned long long wv0 = wp[0], wv1 = wp[1], wv2 = wp[2], wv3 = wp[3];
#pragma unroll
                    for (int q = 0; q < 4; q++) {
                        asm("fma.rn.f32x2 %0, %1, %2, %0;" : "+l"(acc[0][q]) : "l"(xx[kw + q]), "l"(wv0));
                        asm("fma.rn.f32x2 %0, %1, %2, %0;" : "+l"(acc[1][q]) : "l"(xx[kw + q]), "l"(wv1));
                        asm("fma.rn.f32x2 %0, %1, %2, %0;" : "+l"(acc[2][q]) : "l"(xx[kw + q]), "l"(wv2));
                        asm("fma.rn.f32x2 %0, %1, %2, %0;" : "+l"(acc[3][q]) : "l"(xx[kw + q]), "l"(wv3));
                    }
                }
            }
        }
        __syncthreads();
        if (k + 2 < NCHUNK) stage(k + 2, b);
    }

    // ---- epilogue ----
    const int h = h0 + ty;
#pragma unroll
    for (int j = 0; j < 4; j++) {
        int oc0 = ocg * 8 + 2 * j;
        float* o0 = out + ((size_t)(n * COUT + oc0) * PLANE) + h * HW + w0 + tx4;
        float* o1 = o0 + PLANE;
#pragma unroll
        for (int q = 0; q < 4; q++) {
            unsigned lo, hi;
            asm("mov.b64 {%0, %1}, %2;" : "=r"(lo), "=r"(hi) : "l"(acc[j][q]));
            o0[q] = __uint_as_float(lo);
            o1[q] = __uint_as_float(hi);
        }
    }
}

extern "C" void kernel_launch(void* const* d_in, const int* in_sizes, int n_in,
                              void* d_out, int out_size) {
    // inputs: x_slice, out_map(unused), bn_weight, bn_bias, running_mean,
    //         running_var, conv_weight, write_offset(unused)
    const float* x     = (const float*)d_in[0];
    const float* gamma = (const float*)d_in[2];
    const float* beta  = (const float*)d_in[3];
    const float* rmean = (const float*)d_in[4];
    const float* rvar  = (const float*)d_in[5];
    const float* cw    = (const float*)d_in[6];
    float* out = (float*)d_out;

    bn_relu_pad<<<32 * CIN, 256>>>(x, gamma, beta, rmean, rvar);
    wt_transpose<<<(CIN * 9 * COUT + 255) / 256, 256>>>(cw);

    dim3 grid(HW / TW, HW / TH, 32);   // (2, 7, 32) = 448 CTAs
    conv3x3_async<<<grid, NTHREADS>>>(out);
}

// round 8
// speedup vs baseline: 1.9166x; 1.9166x over previous
#include <cuda_runtime.h>
#include <cstdint>

#define CIN    512
#define COUT   32
#define HW     56
#define PLANE  3136
#define HP     58
#define WG     68
#define NCC    16
#define A_FL   (6 * WG * 32)        // 13056 floats per A buffer
#define B_FL   9216                 // floats per B buffer (9*4*4*64)
#define SMEM_FL (2 * A_FL + 2 * B_FL)
#define SMEM_DYN (SMEM_FL * 4)      // 178176 B

__device__ __align__(128) float g_xt[(size_t)32 * NCC * HP * WG * 32];
__device__ __align__(128) float g_wt[NCC * B_FL];   // [cc][tap][ks][nt][k8][oc8]

__device__ __forceinline__ unsigned smem_u32(const void* p) {
    unsigned a;
    asm("{ .reg .u64 t; cvta.to.shared.u64 t, %1; cvt.u32.u64 %0, t; }" : "=r"(a) : "l"(p));
    return a;
}
__device__ __forceinline__ void cp16(unsigned dst, const float* src) {
    asm volatile("cp.async.cg.shared.global [%0], [%1], 16;" :: "r"(dst), "l"(src));
}
__device__ __forceinline__ float tf32r(float v) {
    unsigned u;
    asm("cvt.rna.tf32.f32 %0, %1;" : "=r"(u) : "f"(v));
    return __uint_as_float(u);
}
__device__ __forceinline__ void mma8(float* d, const unsigned* a, unsigned b0, unsigned b1) {
    asm volatile(
        "mma.sync.aligned.m16n8k8.row.col.f32.tf32.tf32.f32 "
        "{%0,%1,%2,%3}, {%4,%5,%6,%7}, {%8,%9}, {%0,%1,%2,%3};"
        : "+f"(d[0]), "+f"(d[1]), "+f"(d[2]), "+f"(d[3])
        : "r"(a[0]), "r"(a[1]), "r"(a[2]), "r"(a[3]), "r"(b0), "r"(b1));
}

// ---------- Kernel 1: BN + ReLU + NCHW -> padded [n][cc][hp][wg][c] tf32 ----------
__global__ __launch_bounds__(256) void bn_relu_tr(
    const float* __restrict__ x, const float* __restrict__ gamma,
    const float* __restrict__ beta, const float* __restrict__ rmean,
    const float* __restrict__ rvar)
{
    __shared__ float sp[4][56][33];
    __shared__ float ssc[32], ssh[32];
    const int b = blockIdx.x;
    const int hb = b % 15, cc = (b / 15) & 15, n = b / 240;
    const int tid = threadIdx.x;

    if (tid < 32) {
        int c = cc * 32 + tid;
        float inv = rsqrtf(rvar[c] + 1e-5f);
        float sc = gamma[c] * inv;
        ssc[tid] = sc;
        ssh[tid] = fmaf(-rmean[c], sc, beta[c]);
    }
    __syncthreads();

    const float* xb = x + ((size_t)n * CIN + cc * 32) * PLANE;
    for (int i = tid; i < 32 * 4 * 14; i += 256) {
        int c = i / 56, r = i % 56;
        int hl = r / 14, w4 = r % 14;
        int h = hb * 4 + hl - 1;
        bool ok = (h >= 0 && h < HW);
        float4 v = make_float4(0.f, 0.f, 0.f, 0.f);
        if (ok) v = *(const float4*)(xb + c * PLANE + h * HW + w4 * 4);
        float vv[4] = {v.x, v.y, v.z, v.w};
#pragma unroll
        for (int q = 0; q < 4; q++) {
            float t = ok ? fmaxf(fmaf(vv[q], ssc[c], ssh[c]), 0.0f) : 0.0f;
            sp[hl][w4 * 4 + q][c] = tf32r(t);
        }
    }
    __syncthreads();

    const int wid = tid >> 5, lane = tid & 31;
    for (int it = wid; it < 4 * WG; it += 8) {
        int dhp = it / WG, wg = it % WG;
        int hp = hb * 4 + dhp;
        if (hp < HP) {
            float v = (wg >= 2 && wg < 58) ? sp[dhp][wg - 2][lane] : 0.0f;
            g_xt[(((size_t)(n * NCC + cc) * HP + hp) * WG + wg) * 32 + lane] = v;
        }
    }
}

// ---------- Kernel 2: weights -> [cc][tap][ks][nt][k8][oc8] tf32 ----------
__global__ __launch_bounds__(256) void wt_prep(const float* __restrict__ cw)
{
    int i = blockIdx.x * 256 + threadIdx.x;
    if (i >= NCC * B_FL) return;
    int cc  = i / B_FL;
    int r   = i % B_FL;
    int tap = r >> 10;
    int ks  = (r >> 8) & 3;
    int nt  = (r >> 6) & 3;
    int k   = (r >> 3) & 7;
    int oc8 = r & 7;
    int oc = nt * 8 + oc8;
    int c  = cc * 32 + ks * 8 + k;
    int kh = tap / 3, kw = tap % 3;
    g_wt[i] = tf32r(cw[((size_t)oc * CIN + c) * 9 + kh * 3 + kw]);
}

// ---------- Kernel 3: implicit-GEMM conv via mma.sync tf32 ----------
__global__ __launch_bounds__(256, 1) void conv_mma(float* __restrict__ out)
{
    extern __shared__ __align__(128) float dsm[];
    const int tid = threadIdx.x;
    const int wid = tid >> 5, lane = tid & 31;
    const int gid = lane >> 2, tig = lane & 3;
    const int hprime = wid >> 1;           // 0..3 output-row within CTA
    const int wpbase = (wid & 1) * 32;     // wg half
    const int ht = blockIdx.x, n = blockIdx.y;
    const int h0 = ht * 4;

    const unsigned sbase = smem_u32(dsm);

    float acc[2][4][4];
#pragma unroll
    for (int t = 0; t < 2; t++)
#pragma unroll
        for (int nt = 0; nt < 4; nt++)
#pragma unroll
            for (int q = 0; q < 4; q++) acc[t][nt][q] = 0.0f;

    auto stage = [&](int cc, int buf) {
        const float* xs = g_xt + (((size_t)(n * NCC + cc)) * HP + h0) * WG * 32;
        const float* ws = g_wt + cc * B_FL;
        unsigned ab = sbase + (unsigned)(buf * A_FL) * 4u;
        unsigned bb = sbase + (unsigned)(2 * A_FL + buf * B_FL) * 4u;
        // A: 6*68 rows x 8 granules, xor-swizzled by wg&7
#pragma unroll
        for (int s = 0; s < 13; s++) {
            int id = tid + s * 256;
            if (s < 12 || tid < (6 * WG * 8 - 12 * 256)) {
                int row = id >> 3, g = id & 7;
                unsigned wgm = ((unsigned)row % WG) & 7u;
                cp16(ab + (unsigned)row * 128u + ((unsigned)(g ^ (int)wgm)) * 16u,
                     xs + row * 32 + g * 4);
            }
        }
        // B: contiguous 2304 x 16B
#pragma unroll
        for (int s = 0; s < 9; s++) {
            int id = tid + s * 256;
            cp16(bb + (unsigned)id * 16u, ws + id * 4);
        }
        asm volatile("cp.async.commit_group;" ::: "memory");
    };

    stage(0, 0);
    stage(1, 1);

#pragma unroll 1
    for (int cc = 0; cc < NCC; cc++) {
        if (cc < NCC - 1) asm volatile("cp.async.wait_group 1;" ::: "memory");
        else              asm volatile("cp.async.wait_group 0;" ::: "memory");
        __syncthreads();
        const int buf = cc & 1;
        const float* sa = dsm + buf * A_FL;
        const float* sb = dsm + 2 * A_FL + buf * B_FL;

#pragma unroll
        for (int kh = 0; kh < 3; kh++) {
#pragma unroll
            for (int kw = 0; kw < 3; kw++) {
                int rbase = (hprime + kh) * (WG * 32);
                int ro[4], wgm[4];
#pragma unroll
                for (int u = 0; u < 4; u++) {       // u = t*2 + s
                    int wg = wpbase + gid + kw + (u & 1) * 8 + (u >> 1) * 16;
                    ro[u]  = rbase + wg * 32 + tig;
                    wgm[u] = wg & 7;
                }
#pragma unroll
                for (int ks = 0; ks < 4; ks++) {
                    unsigned a[2][4];
#pragma unroll
                    for (int t = 0; t < 2; t++) {
                        int u0 = t * 2, u1 = t * 2 + 1;
                        a[t][0] = *(const unsigned*)(sa + ro[u0] + (((2 * ks)     ^ wgm[u0]) << 2));
                        a[t][1] = *(const unsigned*)(sa + ro[u1] + (((2 * ks)     ^ wgm[u1]) << 2));
                        a[t][2] = *(const unsigned*)(sa + ro[u0] + (((2 * ks + 1) ^ wgm[u0]) << 2));
                        a[t][3] = *(const unsigned*)(sa + ro[u1] + (((2 * ks + 1) ^ wgm[u1]) << 2));
                    }
                    const float* bbp = sb + ((kh * 3 + kw) * 4 + ks) * 256;
#pragma unroll
                    for (int nt = 0; nt < 4; nt++) {
                        unsigned b0 = *(const unsigned*)(bbp + nt * 64 + tig * 8 + gid);
                        unsigned b1 = *(const unsigned*)(bbp + nt * 64 + 32 + tig * 8 + gid);
                        mma8(acc[0][nt], a[0], b0, b1);
                        mma8(acc[1][nt], a[1], b0, b1);
                    }
                }
            }
        }
        __syncthreads();
        if (cc + 2 < NCC) stage(cc + 2, buf);
    }

    // ---- epilogue: D[row=pixel][col=oc] -> out[n][oc][h][w] ----
    float* ob = out + (size_t)n * COUT * PLANE + (h0 + hprime) * HW;
#pragma unroll
    for (int t = 0; t < 2; t++) {
        int wpA = wpbase + t * 16 + gid;
        int wpB = wpA + 8;
#pragma unroll
        for (int nt = 0; nt < 4; nt++) {
            int oc = nt * 8 + tig * 2;
            if (wpA >= 1 && wpA <= 56) {
                ob[(size_t)oc * PLANE + (wpA - 1)]       = acc[t][nt][0];
                ob[(size_t)(oc + 1) * PLANE + (wpA - 1)] = acc[t][nt][1];
            }
            if (wpB >= 1 && wpB <= 56) {
                ob[(size_t)oc * PLANE + (wpB - 1)]       = acc[t][nt][2];
                ob[(size_t)(oc + 1) * PLANE + (wpB - 1)] = acc[t][nt][3];
            }
        }
    }
}

extern "C" void kernel_launch(void* const* d_in, const int* in_sizes, int n_in,
                              void* d_out, int out_size) {
    // inputs: x_slice, out_map(unused), bn_weight, bn_bias, running_mean,
    //         running_var, conv_weight, write_offset(unused)
    const float* x     = (const float*)d_in[0];
    const float* gamma = (const float*)d_in[2];
    const float* beta  = (const float*)d_in[3];
    const float* rmean = (const float*)d_in[4];
    const float* rvar  = (const float*)d_in[5];
    const float* cw    = (const float*)d_in[6];
    float* out = (float*)d_out;

    cudaFuncSetAttribute(conv_mma, cudaFuncAttributeMaxDynamicSharedMemorySize, SMEM_DYN);

    bn_relu_tr<<<32 * NCC * 15, 256>>>(x, gamma, beta, rmean, rvar);
    wt_prep<<<(NCC * B_FL + 255) / 256, 256>>>(cw);
    conv_mma<<<dim3(14, 32), 256, SMEM_DYN>>>(out);
}

// round 9
// speedup vs baseline: 2.0231x; 1.0556x over previous
#include <cuda_runtime.h>
#include <cstdint>

#define CIN    512
#define COUT   32
#define HW     56
#define PLANE  3136
#define HP     58
#define WG     68
#define NCC    16
#define AROW   36                    // padded floats per A row (32 data + 4 pad)
#define A_FL   (6 * WG * AROW)       // 14688 floats per A buffer
#define B_FL   9216                  // floats per B buffer
#define BOFF   (2 * A_FL)
#define SMEM_DYN ((2 * A_FL + 2 * B_FL) * 4)   // 191232 B

__device__ __align__(128) float g_xt[(size_t)32 * NCC * HP * WG * 32];
__device__ __align__(128) float g_wt[NCC * B_FL];

__device__ __forceinline__ unsigned smem_u32(const void* p) {
    unsigned a;
    asm("{ .reg .u64 t; cvta.to.shared.u64 t, %1; cvt.u32.u64 %0, t; }" : "=r"(a) : "l"(p));
    return a;
}
__device__ __forceinline__ void cp16(unsigned dst, const float* src) {
    asm volatile("cp.async.cg.shared.global [%0], [%1], 16;" :: "r"(dst), "l"(src));
}
__device__ __forceinline__ float tf32r(float v) {
    unsigned u;
    asm("cvt.rna.tf32.f32 %0, %1;" : "=r"(u) : "f"(v));
    return __uint_as_float(u);
}
__device__ __forceinline__ void mma8(float* d, const unsigned* a, unsigned b0, unsigned b1) {
    asm volatile(
        "mma.sync.aligned.m16n8k8.row.col.f32.tf32.tf32.f32 "
        "{%0,%1,%2,%3}, {%4,%5,%6,%7}, {%8,%9}, {%0,%1,%2,%3};"
        : "+f"(d[0]), "+f"(d[1]), "+f"(d[2]), "+f"(d[3])
        : "r"(a[0]), "r"(a[1]), "r"(a[2]), "r"(a[3]), "r"(b0), "r"(b1));
}

// ---------- Kernel 1: BN + ReLU + NCHW -> padded [n][cc][hp][wg][sigma(c)] tf32 ----------
__global__ __launch_bounds__(256) void bn_relu_tr(
    const float* __restrict__ x, const float* __restrict__ gamma,
    const float* __restrict__ beta, const float* __restrict__ rmean,
    const float* __restrict__ rvar)
{
    __shared__ float sp[4][56][33];
    __shared__ float ssc[32], ssh[32];
    const int b = blockIdx.x;
    const int hb = b % 15, cc = (b / 15) & 15, n = b / 240;
    const int tid = threadIdx.x;

    if (tid < 32) {
        int c = cc * 32 + tid;
        float inv = rsqrtf(rvar[c] + 1e-5f);
        float sc = gamma[c] * inv;
        ssc[tid] = sc;
        ssh[tid] = fmaf(-rmean[c], sc, beta[c]);
    }
    __syncthreads();

    const float* xb = x + ((size_t)n * CIN + cc * 32) * PLANE;
#pragma unroll
    for (int s = 0; s < 7; s++) {           // 7*256 = 1792 exact
        int i = tid + s * 256;
        int c = i / 56, r = i % 56;
        int hl = r / 14, w4 = r % 14;
        int h = hb * 4 + hl - 1;
        bool ok = (h >= 0 && h < HW);
        float4 v = make_float4(0.f, 0.f, 0.f, 0.f);
        if (ok) v = *(const float4*)(xb + c * PLANE + h * HW + w4 * 4);
        float vv[4] = {v.x, v.y, v.z, v.w};
#pragma unroll
        for (int q = 0; q < 4; q++) {
            float t = ok ? fmaxf(fmaf(vv[q], ssc[c], ssh[c]), 0.0f) : 0.0f;
            sp[hl][w4 * 4 + q][c] = tf32r(t);
        }
    }
    __syncthreads();

    const int wid = tid >> 5, lane = tid & 31;
    const int slot = ((lane & 3) << 3) | (lane >> 2);   // sigma(c): fragment-friendly order
#pragma unroll
    for (int dhp = 0; dhp < 4; dhp++) {
        int hp = hb * 4 + dhp;
        if (hp < HP) {
            float* orow = g_xt + (((size_t)(n * NCC + cc) * HP + hp) * WG) * 32 + slot;
#pragma unroll
            for (int j = 0; j < 9; j++) {
                int wg = wid + j * 8;
                if (j < 8 || wid < 4) {     // wg < 68
                    float v = 0.0f;
                    if (wg >= 2 && wg < 58) v = sp[dhp][wg - 2][lane];
                    orow[wg * 32] = v;
                }
            }
        }
    }
}

// ---------- Kernel 2: weights -> [cc][tap][ks][half][lane][nt] tf32 ----------
__global__ __launch_bounds__(256) void wt_prep(const float* __restrict__ cw)
{
    int i = blockIdx.x * 256 + threadIdx.x;
    if (i >= NCC * B_FL) return;
    int nt   = i & 3;
    int lane = (i >> 2) & 31;
    int h    = (i >> 7) & 1;
    int ks   = (i >> 8) & 3;
    int tc   = i >> 10;
    int tap  = tc % 9, cc = tc / 9;
    int oc = nt * 8 + (lane >> 2);
    int k  = ks * 8 + (lane & 3) + h * 4;
    int c  = cc * 32 + k;
    int kh = tap / 3, kw = tap % 3;
    g_wt[i] = tf32r(cw[((size_t)oc * CIN + c) * 9 + kh * 3 + kw]);
}

// ---------- Kernel 3: implicit-GEMM conv via mma.sync tf32 (vector LDS) ----------
__global__ __launch_bounds__(256, 1) void conv_mma(float* __restrict__ out)
{
    extern __shared__ __align__(128) float dsm[];
    const int tid = threadIdx.x;
    const int wid = tid >> 5, lane = tid & 31;
    const int gid = lane >> 2, tig = lane & 3;
    const int hprime = wid >> 1;
    const int wpbase = (wid & 1) * 32;
    const int ht = blockIdx.x, n = blockIdx.y;
    const int h0 = ht * 4;

    const unsigned sbase = smem_u32(dsm);

    float acc[2][4][4];
#pragma unroll
    for (int t = 0; t < 2; t++)
#pragma unroll
        for (int nt = 0; nt < 4; nt++)
#pragma unroll
            for (int q = 0; q < 4; q++) acc[t][nt][q] = 0.0f;

    auto stage = [&](int cc, int buf) {
        const float* xs = g_xt + ((size_t)(n * NCC + cc) * HP + h0) * WG * 32;
        const float* ws = g_wt + cc * B_FL;
        unsigned ab = sbase + (unsigned)(buf * A_FL) * 4u;
        unsigned bb = sbase + (unsigned)(BOFF + buf * B_FL) * 4u;
        // A: 408 rows x 8 granules; dest rows padded to 144B
#pragma unroll
        for (int s = 0; s < 13; s++) {
            int id = tid + s * 256;
            if (s < 12 || tid < 192) {      // id < 3264
                int row = id >> 3, g = id & 7;
                cp16(ab + (unsigned)row * 144u + (unsigned)g * 16u,
                     xs + row * 32 + g * 4);
            }
        }
        // B: contiguous 2304 x 16B
#pragma unroll
        for (int s = 0; s < 9; s++) {
            int id = tid + s * 256;
            cp16(bb + (unsigned)id * 16u, ws + id * 4);
        }
        asm volatile("cp.async.commit_group;" ::: "memory");
    };

    stage(0, 0);
    stage(1, 1);

#pragma unroll 1
    for (int cc = 0; cc < NCC; cc++) {
        if (cc < NCC - 1) asm volatile("cp.async.wait_group 1;" ::: "memory");
        else              asm volatile("cp.async.wait_group 0;" ::: "memory");
        __syncthreads();
        const int buf = cc & 1;
        const float* sa = dsm + buf * A_FL;
        const float* sb = dsm + BOFF + buf * B_FL;

#pragma unroll
        for (int kh = 0; kh < 3; kh++) {
            const float* sarow = sa + (hprime + kh) * (WG * AROW);
#pragma unroll
            for (int kw = 0; kw < 3; kw++) {
                // load 4 fragment rows, 8 floats each, as float4 pairs
                float r[4][8];
#pragma unroll
                for (int u = 0; u < 4; u++) {
                    int wg = wpbase + gid + kw + (u & 1) * 8 + (u >> 1) * 16;
                    const float* rp = sarow + wg * AROW + tig * 8;
                    float4 p = *(const float4*)rp;
                    float4 q = *(const float4*)(rp + 4);
                    r[u][0] = p.x; r[u][1] = p.y; r[u][2] = p.z; r[u][3] = p.w;
                    r[u][4] = q.x; r[u][5] = q.y; r[u][6] = q.z; r[u][7] = q.w;
                }
                const float* bbp = sb + (kh * 3 + kw) * 1024 + lane * 4;
#pragma unroll
                for (int ks = 0; ks < 4; ks++) {
                    float4 b0 = *(const float4*)(bbp + ks * 256);
                    float4 b1 = *(const float4*)(bbp + ks * 256 + 128);
                    float bb0[4] = {b0.x, b0.y, b0.z, b0.w};
                    float bb1[4] = {b1.x, b1.y, b1.z, b1.w};
#pragma unroll
                    for (int t = 0; t < 2; t++) {
                        unsigned a[4];
                        a[0] = __float_as_uint(r[t * 2][2 * ks]);
                        a[1] = __float_as_uint(r[t * 2 + 1][2 * ks]);
                        a[2] = __float_as_uint(r[t * 2][2 * ks + 1]);
                        a[3] = __float_as_uint(r[t * 2 + 1][2 * ks + 1]);
#pragma unroll
                        for (int nt = 0; nt < 4; nt++)
                            mma8(acc[t][nt], a,
                                 __float_as_uint(bb0[nt]), __float_as_uint(bb1[nt]));
                    }
                }
            }
        }
        __syncthreads();
        if (cc + 2 < NCC) stage(cc + 2, buf);
    }

    // ---- epilogue ----
    float* ob = out + (size_t)n * COUT * PLANE + (h0 + hprime) * HW;
#pragma unroll
    for (int t = 0; t < 2; t++) {
        int wpA = wpbase + t * 16 + gid;
        int wpB = wpA + 8;
#pragma unroll
        for (int nt = 0; nt < 4; nt++) {
            int oc = nt * 8 + tig * 2;
            if (wpA >= 1 && wpA <= 56) {
                ob[(size_t)oc * PLANE + (wpA - 1)]       = acc[t][nt][0];
                ob[(size_t)(oc + 1) * PLANE + (wpA - 1)] = acc[t][nt][1];
            }
            if (wpB >= 1 && wpB <= 56) {
                ob[(size_t)oc * PLANE + (wpB - 1)]       = acc[t][nt][2];
                ob[(size_t)(oc + 1) * PLANE + (wpB - 1)] = acc[t][nt][3];
            }
        }
    }
}

extern "C" void kernel_launch(void* const* d_in, const int* in_sizes, int n_in,
                              void* d_out, int out_size) {
    // inputs: x_slice, out_map(unused), bn_weight, bn_bias, running_mean,
    //         running_var, conv_weight, write_offset(unused)
    const float* x     = (const float*)d_in[0];
    const float* gamma = (const float*)d_in[2];
    const float* beta  = (const float*)d_in[3];
    const float* rmean = (const float*)d_in[4];
    const float* rvar  = (const float*)d_in[5];
    const float* cw    = (const float*)d_in[6];
    float* out = (float*)d_out;

    cudaFuncSetAttribute(conv_mma, cudaFuncAttributeMaxDynamicSharedMemorySize, SMEM_DYN);

    bn_relu_tr<<<32 * NCC * 15, 256>>>(x, gamma, beta, rmean, rvar);
    wt_prep<<<(NCC * B_FL + 255) / 256, 256>>>(cw);
    conv_mma<<<dim3(14, 32), 256, SMEM_DYN>>>(out);
}

// round 10
// speedup vs baseline: 2.3915x; 1.1821x over previous
#include <cuda_runtime.h>
#include <cstdint>

#define CIN    512
#define COUT   32
#define HW     56
#define PLANE  3136
#define HP     58
#define WG     68
#define NCC    16
#define A_FL   (6 * WG * 32)        // 13056 floats per A buffer
#define B_FL   9216                 // floats per B buffer (9*4*4*64)
#define SMEM_FL (2 * A_FL + 2 * B_FL)
#define SMEM_DYN (SMEM_FL * 4)      // 178176 B

__device__ __align__(128) float g_xt[(size_t)32 * NCC * HP * WG * 32];
__device__ __align__(128) float g_wt[NCC * B_FL];   // [cc][tap][ks][nt][k8][oc8]

__device__ __forceinline__ unsigned smem_u32(const void* p) {
    unsigned a;
    asm("{ .reg .u64 t; cvta.to.shared.u64 t, %1; cvt.u32.u64 %0, t; }" : "=r"(a) : "l"(p));
    return a;
}
__device__ __forceinline__ void cp16(unsigned dst, const float* src) {
    asm volatile("cp.async.cg.shared.global [%0], [%1], 16;" :: "r"(dst), "l"(src));
}
__device__ __forceinline__ float tf32r(float v) {
    unsigned u;
    asm("cvt.rna.tf32.f32 %0, %1;" : "=r"(u) : "f"(v));
    return __uint_as_float(u);
}
__device__ __forceinline__ void mma8(float* d, const unsigned* a, unsigned b0, unsigned b1) {
    asm volatile(
        "mma.sync.aligned.m16n8k8.row.col.f32.tf32.tf32.f32 "
        "{%0,%1,%2,%3}, {%4,%5,%6,%7}, {%8,%9}, {%0,%1,%2,%3};"
        : "+f"(d[0]), "+f"(d[1]), "+f"(d[2]), "+f"(d[3])
        : "r"(a[0]), "r"(a[1]), "r"(a[2]), "r"(a[3]), "r"(b0), "r"(b1));
}

// ---------- Kernel 1: BN + ReLU + NCHW -> padded [n][cc][hp][wg][c] tf32 ----------
// (R9 affine-index version; slot = lane, matching the R8 conv layout)
__global__ __launch_bounds__(256) void bn_relu_tr(
    const float* __restrict__ x, const float* __restrict__ gamma,
    const float* __restrict__ beta, const float* __restrict__ rmean,
    const float* __restrict__ rvar)
{
    __shared__ float sp[4][56][33];
    __shared__ float ssc[32], ssh[32];
    const int b = blockIdx.x;
    const int hb = b % 15, cc = (b / 15) & 15, n = b / 240;
    const int tid = threadIdx.x;

    if (tid < 32) {
        int c = cc * 32 + tid;
        float inv = rsqrtf(rvar[c] + 1e-5f);
        float sc = gamma[c] * inv;
        ssc[tid] = sc;
        ssh[tid] = fmaf(-rmean[c], sc, beta[c]);
    }
    __syncthreads();

    const float* xb = x + ((size_t)n * CIN + cc * 32) * PLANE;
#pragma unroll
    for (int s = 0; s < 7; s++) {           // 7*256 = 1792 exact
        int i = tid + s * 256;
        int c = i / 56, r = i % 56;
        int hl = r / 14, w4 = r % 14;
        int h = hb * 4 + hl - 1;
        bool ok = (h >= 0 && h < HW);
        float4 v = make_float4(0.f, 0.f, 0.f, 0.f);
        if (ok) v = *(const float4*)(xb + c * PLANE + h * HW + w4 * 4);
        float vv[4] = {v.x, v.y, v.z, v.w};
#pragma unroll
        for (int q = 0; q < 4; q++) {
            float t = ok ? fmaxf(fmaf(vv[q], ssc[c], ssh[c]), 0.0f) : 0.0f;
            sp[hl][w4 * 4 + q][c] = tf32r(t);
        }
    }
    __syncthreads();

    const int wid = tid >> 5, lane = tid & 31;
#pragma unroll
    for (int dhp = 0; dhp < 4; dhp++) {
        int hp = hb * 4 + dhp;
        if (hp < HP) {
            float* orow = g_xt + (((size_t)(n * NCC + cc) * HP + hp) * WG) * 32 + lane;
#pragma unroll
            for (int j = 0; j < 9; j++) {
                int wg = wid + j * 8;
                if (j < 8 || wid < 4) {     // wg < 68
                    float v = 0.0f;
                    if (wg >= 2 && wg < 58) v = sp[dhp][wg - 2][lane];
                    orow[wg * 32] = v;
                }
            }
        }
    }
}

// ---------- Kernel 2: weights -> [cc][tap][ks][nt][k8][oc8] tf32 ----------
__global__ __launch_bounds__(256) void wt_prep(const float* __restrict__ cw)
{
    int i = blockIdx.x * 256 + threadIdx.x;
    if (i >= NCC * B_FL) return;
    int cc  = i / B_FL;
    int r   = i % B_FL;
    int tap = r >> 10;
    int ks  = (r >> 8) & 3;
    int nt  = (r >> 6) & 3;
    int k   = (r >> 3) & 7;
    int oc8 = r & 7;
    int oc = nt * 8 + oc8;
    int c  = cc * 32 + ks * 8 + k;
    int kh = tap / 3, kw = tap % 3;
    g_wt[i] = tf32r(cw[((size_t)oc * CIN + c) * 9 + kh * 3 + kw]);
}

// ---------- Kernel 3: implicit-GEMM conv via mma.sync tf32 (R8 version) ----------
__global__ __launch_bounds__(256, 1) void conv_mma(float* __restrict__ out)
{
    extern __shared__ __align__(128) float dsm[];
    const int tid = threadIdx.x;
    const int wid = tid >> 5, lane = tid & 31;
    const int gid = lane >> 2, tig = lane & 3;
    const int hprime = wid >> 1;           // 0..3 output-row within CTA
    const int wpbase = (wid & 1) * 32;     // wg half
    const int ht = blockIdx.x, n = blockIdx.y;
    const int h0 = ht * 4;

    const unsigned sbase = smem_u32(dsm);

    float acc[2][4][4];
#pragma unroll
    for (int t = 0; t < 2; t++)
#pragma unroll
        for (int nt = 0; nt < 4; nt++)
#pragma unroll
            for (int q = 0; q < 4; q++) acc[t][nt][q] = 0.0f;

    auto stage = [&](int cc, int buf) {
        const float* xs = g_xt + (((size_t)(n * NCC + cc)) * HP + h0) * WG * 32;
        const float* ws = g_wt + cc * B_FL;
        unsigned ab = sbase + (unsigned)(buf * A_FL) * 4u;
        unsigned bb = sbase + (unsigned)(2 * A_FL + buf * B_FL) * 4u;
        // A: 6*68 rows x 8 granules, xor-swizzled by wg&7
#pragma unroll
        for (int s = 0; s < 13; s++) {
            int id = tid + s * 256;
            if (s < 12 || tid < (6 * WG * 8 - 12 * 256)) {
                int row = id >> 3, g = id & 7;
                unsigned wgm = ((unsigned)row % WG) & 7u;
                cp16(ab + (unsigned)row * 128u + ((unsigned)(g ^ (int)wgm)) * 16u,
                     xs + row * 32 + g * 4);
            }
        }
        // B: contiguous 2304 x 16B
#pragma unroll
        for (int s = 0; s < 9; s++) {
            int id = tid + s * 256;
            cp16(bb + (unsigned)id * 16u, ws + id * 4);
        }
        asm volatile("cp.async.commit_group;" ::: "memory");
    };

    stage(0, 0);
    stage(1, 1);

#pragma unroll 1
    for (int cc = 0; cc < NCC; cc++) {
        if (cc < NCC - 1) asm volatile("cp.async.wait_group 1;" ::: "memory");
        else              asm volatile("cp.async.wait_group 0;" ::: "memory");
        __syncthreads();
        const int buf = cc & 1;
        const float* sa = dsm + buf * A_FL;
        const float* sb = dsm + 2 * A_FL + buf * B_FL;

#pragma unroll
        for (int kh = 0; kh < 3; kh++) {
#pragma unroll
            for (int kw = 0; kw < 3; kw++) {
                int rbase = (hprime + kh) * (WG * 32);
                int ro[4], wgm[4];
#pragma unroll
                for (int u = 0; u < 4; u++) {       // u = t*2 + s
                    int wg = wpbase + gid + kw + (u & 1) * 8 + (u >> 1) * 16;
                    ro[u]  = rbase + wg * 32 + tig;
                    wgm[u] = wg & 7;
                }
#pragma unroll
                for (int ks = 0; ks < 4; ks++) {
                    unsigned a[2][4];
#pragma unroll
                    for (int t = 0; t < 2; t++) {
                        int u0 = t * 2, u1 = t * 2 + 1;
                        a[t][0] = *(const unsigned*)(sa + ro[u0] + (((2 * ks)     ^ wgm[u0]) << 2));
                        a[t][1] = *(const unsigned*)(sa + ro[u1] + (((2 * ks)     ^ wgm[u1]) << 2));
                        a[t][2] = *(const unsigned*)(sa + ro[u0] + (((2 * ks + 1) ^ wgm[u0]) << 2));
                        a[t][3] = *(const unsigned*)(sa + ro[u1] + (((2 * ks + 1) ^ wgm[u1]) << 2));
                    }
                    const float* bbp = sb + ((kh * 3 + kw) * 4 + ks) * 256;
#pragma unroll
                    for (int nt = 0; nt < 4; nt++) {
                        unsigned b0 = *(const unsigned*)(bbp + nt * 64 + tig * 8 + gid);
                        unsigned b1 = *(const unsigned*)(bbp + nt * 64 + 32 + tig * 8 + gid);
                        mma8(acc[0][nt], a[0], b0, b1);
                        mma8(acc[1][nt], a[1], b0, b1);
                    }
                }
            }
        }
        __syncthreads();
        if (cc + 2 < NCC) stage(cc + 2, buf);
    }

    // ---- epilogue: D[row=pixel][col=oc] -> out[n][oc][h][w] ----
    float* ob = out + (size_t)n * COUT * PLANE + (h0 + hprime) * HW;
#pragma unroll
    for (int t = 0; t < 2; t++) {
        int wpA = wpbase + t * 16 + gid;
        int wpB = wpA + 8;
#pragma unroll
        for (int nt = 0; nt < 4; nt++) {
            int oc = nt * 8 + tig * 2;
            if (wpA >= 1 && wpA <= 56) {
                ob[(size_t)oc * PLANE + (wpA - 1)]       = acc[t][nt][0];
                ob[(size_t)(oc + 1) * PLANE + (wpA - 1)] = acc[t][nt][1];
            }
            if (wpB >= 1 && wpB <= 56) {
                ob[(size_t)oc * PLANE + (wpB - 1)]       = acc[t][nt][2];
                ob[(size_t)(oc + 1) * PLANE + (wpB - 1)] = acc[t][nt][3];
            }
        }
    }
}

extern "C" void kernel_launch(void* const* d_in, const int* in_sizes, int n_in,
                              void* d_out, int out_size) {
    // inputs: x_slice, out_map(unused), bn_weight, bn_bias, running_mean,
    //         running_var, conv_weight, write_offset(unused)
    const float* x     = (const float*)d_in[0];
    const float* gamma = (const float*)d_in[2];
    const float* beta  = (const float*)d_in[3];
    const float* rmean = (const float*)d_in[4];
    const float* rvar  = (const float*)d_in[5];
    const float* cw    = (const float*)d_in[6];
    float* out = (float*)d_out;

    cudaFuncSetAttribute(conv_mma, cudaFuncAttributeMaxDynamicSharedMemorySize, SMEM_DYN);

    // Order: wt_prep first so ncu's -s 5 -c 1 sample (launch #6) lands on conv_mma.
    wt_prep<<<(NCC * B_FL + 255) / 256, 256>>>(cw);
    bn_relu_tr<<<32 * NCC * 15, 256>>>(x, gamma, beta, rmean, rvar);
    conv_mma<<<dim3(14, 32), 256, SMEM_DYN>>>(out);
}

// round 11
// speedup vs baseline: 2.4884x; 1.0405x over previous
#include <cuda_runtime.h>
#include <cstdint>

#define CIN    512
#define COUT   32
#define HW     56
#define PLANE  3136
#define HP     58
#define WG     68
#define NCC    16
#define A_FL   (6 * WG * 32)        // 13056 floats per A buffer
#define B_FL   9216                 // floats per B buffer (9*4*4*64)
#define SMEM_FL (2 * A_FL + 2 * B_FL)
#define SMEM_DYN (SMEM_FL * 4)      // 178176 B

__device__ __align__(128) float g_xt[(size_t)32 * NCC * HP * WG * 32];
__device__ __align__(128) float g_wt[NCC * B_FL];   // [cc][tap][ks][nt][k8][oc8]

__device__ __forceinline__ unsigned smem_u32(const void* p) {
    unsigned a;
    asm("{ .reg .u64 t; cvta.to.shared.u64 t, %1; cvt.u32.u64 %0, t; }" : "=r"(a) : "l"(p));
    return a;
}
__device__ __forceinline__ void cp16(unsigned dst, const float* src) {
    asm volatile("cp.async.cg.shared.global [%0], [%1], 16;" :: "r"(dst), "l"(src));
}
__device__ __forceinline__ float tf32r(float v) {
    unsigned u;
    asm("cvt.rna.tf32.f32 %0, %1;" : "=r"(u) : "f"(v));
    return __uint_as_float(u);
}
__device__ __forceinline__ void mma8(float* d, const unsigned* a, unsigned b0, unsigned b1) {
    asm volatile(
        "mma.sync.aligned.m16n8k8.row.col.f32.tf32.tf32.f32 "
        "{%0,%1,%2,%3}, {%4,%5,%6,%7}, {%8,%9}, {%0,%1,%2,%3};"
        : "+f"(d[0]), "+f"(d[1]), "+f"(d[2]), "+f"(d[3])
        : "r"(a[0]), "r"(a[1]), "r"(a[2]), "r"(a[3]), "r"(b0), "r"(b1));
}

// ---------- Kernel 1: BN + ReLU + NCHW -> padded [n][cc][hp][wg][c] tf32 ----------
__global__ __launch_bounds__(256) void bn_relu_tr(
    const float* __restrict__ x, const float* __restrict__ gamma,
    const float* __restrict__ beta, const float* __restrict__ rmean,
    const float* __restrict__ rvar)
{
    __shared__ float sp[4][56][33];
    __shared__ float ssc[32], ssh[32];
    const int b = blockIdx.x;
    const int hb = b % 15, cc = (b / 15) & 15, n = b / 240;
    const int tid = threadIdx.x;

    if (tid < 32) {
        int c = cc * 32 + tid;
        float inv = rsqrtf(rvar[c] + 1e-5f);
        float sc = gamma[c] * inv;
        ssc[tid] = sc;
        ssh[tid] = fmaf(-rmean[c], sc, beta[c]);
    }
    __syncthreads();

    const float* xb = x + ((size_t)n * CIN + cc * 32) * PLANE;
#pragma unroll
    for (int s = 0; s < 7; s++) {           // 7*256 = 1792 exact
        int i = tid + s * 256;
        int c = i / 56, r = i % 56;
        int hl = r / 14, w4 = r % 14;
        int h = hb * 4 + hl - 1;
        bool ok = (h >= 0 && h < HW);
        float4 v = make_float4(0.f, 0.f, 0.f, 0.f);
        if (ok) v = *(const float4*)(xb + c * PLANE + h * HW + w4 * 4);
        float vv[4] = {v.x, v.y, v.z, v.w};
#pragma unroll
        for (int q = 0; q < 4; q++) {
            float t = ok ? fmaxf(fmaf(vv[q], ssc[c], ssh[c]), 0.0f) : 0.0f;
            sp[hl][w4 * 4 + q][c] = tf32r(t);
        }
    }
    __syncthreads();

    const int wid = tid >> 5, lane = tid & 31;
#pragma unroll
    for (int dhp = 0; dhp < 4; dhp++) {
        int hp = hb * 4 + dhp;
        if (hp < HP) {
            float* orow = g_xt + (((size_t)(n * NCC + cc) * HP + hp) * WG) * 32 + lane;
#pragma unroll
            for (int j = 0; j < 9; j++) {
                int wg = wid + j * 8;
                if (j < 8 || wid < 4) {     // wg < 68
                    float v = 0.0f;
                    if (wg >= 2 && wg < 58) v = sp[dhp][wg - 2][lane];
                    orow[wg * 32] = v;
                }
            }
        }
    }
}

// ---------- Kernel 2: weights -> [cc][tap][ks][nt][k8][oc8] tf32 ----------
__global__ __launch_bounds__(256) void wt_prep(const float* __restrict__ cw)
{
    int i = blockIdx.x * 256 + threadIdx.x;
    if (i >= NCC * B_FL) return;
    int cc  = i / B_FL;
    int r   = i % B_FL;
    int tap = r >> 10;
    int ks  = (r >> 8) & 3;
    int nt  = (r >> 6) & 3;
    int k   = (r >> 3) & 7;
    int oc8 = r & 7;
    int oc = nt * 8 + oc8;
    int c  = cc * 32 + ks * 8 + k;
    int kh = tap / 3, kw = tap % 3;
    g_wt[i] = tf32r(cw[((size_t)oc * CIN + c) * 9 + kh * 3 + kw]);
}

// ---------- Kernel 3: implicit-GEMM conv, K-split warps, mma.sync tf32 ----------
__global__ __launch_bounds__(256, 1) void conv_mma(float* __restrict__ out)
{
    extern __shared__ __align__(128) float dsm[];
    const int tid = threadIdx.x;
    const int wid = tid >> 5, lane = tid & 31;
    const int gid = lane >> 2, tig = lane & 3;
    const int hp  = wid >> 1;          // output h-row within CTA (0..3)
    const int ksh = wid & 1;           // K-split half (ks 0-1 vs 2-3)
    const int ht = blockIdx.x, n = blockIdx.y;
    const int h0 = ht * 4;

    const unsigned sbase = smem_u32(dsm);

    float acc[4][4][4];                // [m-tile][n-tile][quad]
#pragma unroll
    for (int mt = 0; mt < 4; mt++)
#pragma unroll
        for (int nt = 0; nt < 4; nt++)
#pragma unroll
            for (int q = 0; q < 4; q++) acc[mt][nt][q] = 0.0f;

    auto stage = [&](int cc, int buf) {
        const float* xs = g_xt + (((size_t)(n * NCC + cc)) * HP + h0) * WG * 32;
        const float* ws = g_wt + cc * B_FL;
        unsigned ab = sbase + (unsigned)(buf * A_FL) * 4u;
        unsigned bb = sbase + (unsigned)(2 * A_FL + buf * B_FL) * 4u;
        // A: 6*68 rows x 8 granules, xor-swizzled by wg&7
#pragma unroll
        for (int s = 0; s < 13; s++) {
            int id = tid + s * 256;
            if (s < 12 || tid < 192) {      // id < 3264
                int row = id >> 3, g = id & 7;
                unsigned wgm = ((unsigned)row % WG) & 7u;
                cp16(ab + (unsigned)row * 128u + ((unsigned)(g ^ (int)wgm)) * 16u,
                     xs + row * 32 + g * 4);
            }
        }
        // B: contiguous 2304 x 16B
#pragma unroll
        for (int s = 0; s < 9; s++) {
            int id = tid + s * 256;
            cp16(bb + (unsigned)id * 16u, ws + id * 4);
        }
        asm volatile("cp.async.commit_group;" ::: "memory");
    };

    stage(0, 0);
    stage(1, 1);

#pragma unroll 1
    for (int cc = 0; cc < NCC; cc++) {
        if (cc < NCC - 1) asm volatile("cp.async.wait_group 1;" ::: "memory");
        else              asm volatile("cp.async.wait_group 0;" ::: "memory");
        __syncthreads();
        const int buf = cc & 1;
        const float* sa = dsm + buf * A_FL;
        const float* sb = dsm + 2 * A_FL + buf * B_FL;

#pragma unroll
        for (int kh = 0; kh < 3; kh++) {
            const float* sarow = sa + (hp + kh) * (WG * 32);
#pragma unroll
            for (int kw = 0; kw < 3; kw++) {
                int ro[4][2], wm[4][2];
#pragma unroll
                for (int mt = 0; mt < 4; mt++) {
                    int wg0 = mt * 16 + gid + kw;
                    int wg1 = wg0 + 8;
                    ro[mt][0] = wg0 * 32 + tig;  wm[mt][0] = wg0 & 7;
                    ro[mt][1] = wg1 * 32 + tig;  wm[mt][1] = wg1 & 7;
                }
                const float* bbp = sb + (kh * 3 + kw) * 1024 + tig * 8 + gid;
#pragma unroll
                for (int s = 0; s < 2; s++) {
                    const int ks = ksh * 2 + s;
                    const int g0 = 2 * ks, g1 = 2 * ks + 1;
                    unsigned b0[4], b1[4];
                    const float* bp = bbp + ks * 256;
#pragma unroll
                    for (int nt = 0; nt < 4; nt++) {
                        b0[nt] = *(const unsigned*)(bp + nt * 64);
                        b1[nt] = *(const unsigned*)(bp + nt * 64 + 32);
                    }
#pragma unroll
                    for (int mt = 0; mt < 4; mt++) {
                        unsigned a[4];
                        a[0] = *(const unsigned*)(sarow + ro[mt][0] + ((g0 ^ wm[mt][0]) << 2));
                        a[1] = *(const unsigned*)(sarow + ro[mt][1] + ((g0 ^ wm[mt][1]) << 2));
                        a[2] = *(const unsigned*)(sarow + ro[mt][0] + ((g1 ^ wm[mt][0]) << 2));
                        a[3] = *(const unsigned*)(sarow + ro[mt][1] + ((g1 ^ wm[mt][1]) << 2));
#pragma unroll
                        for (int nt = 0; nt < 4; nt++)
                            mma8(acc[mt][nt], a, b0[nt], b1[nt]);
                    }
                }
            }
        }
        __syncthreads();
        if (cc + 2 < NCC) stage(cc + 2, buf);
    }

    // ---- K-split reduction: odd warps dump partials, even warps merge + store ----
    __syncthreads();
    float* red = dsm;                       // reuse A buffer (synced above)
    const int rbase = (hp * 32 + lane) * 65;
    if (ksh) {
#pragma unroll
        for (int mt = 0; mt < 4; mt++)
#pragma unroll
            for (int nt = 0; nt < 4; nt++)
#pragma unroll
                for (int q = 0; q < 4; q++)
                    red[rbase + (mt * 4 + nt) * 4 + q] = acc[mt][nt][q];
    }
    __syncthreads();
    if (!ksh) {
        float* ob = out + (size_t)n * COUT * PLANE + (h0 + hp) * HW;
#pragma unroll
        for (int mt = 0; mt < 4; mt++) {
            int wpA = mt * 16 + gid;
            int wpB = wpA + 8;
#pragma unroll
            for (int nt = 0; nt < 4; nt++) {
                float v0 = acc[mt][nt][0] + red[rbase + (mt * 4 + nt) * 4 + 0];
                float v1 = acc[mt][nt][1] + red[rbase + (mt * 4 + nt) * 4 + 1];
                float v2 = acc[mt][nt][2] + red[rbase + (mt * 4 + nt) * 4 + 2];
                float v3 = acc[mt][nt][3] + red[rbase + (mt * 4 + nt) * 4 + 3];
                int oc = nt * 8 + tig * 2;
                if (wpA >= 1 && wpA <= 56) {
                    ob[(size_t)oc * PLANE + (wpA - 1)]       = v0;
                    ob[(size_t)(oc + 1) * PLANE + (wpA - 1)] = v1;
                }
                if (wpB >= 1 && wpB <= 56) {
                    ob[(size_t)oc * PLANE + (wpB - 1)]       = v2;
                    ob[(size_t)(oc + 1) * PLANE + (wpB - 1)] = v3;
                }
            }
        }
    }
}

// 4th launch per replay: shifts ncu's capture (launch index 6) onto conv_mma.
__global__ void knop() {}

extern "C" void kernel_launch(void* const* d_in, const int* in_sizes, int n_in,
                              void* d_out, int out_size) {
    // inputs: x_slice, out_map(unused), bn_weight, bn_bias, running_mean,
    //         running_var, conv_weight, write_offset(unused)
    const float* x     = (const float*)d_in[0];
    const float* gamma = (const float*)d_in[2];
    const float* beta  = (const float*)d_in[3];
    const float* rmean = (const float*)d_in[4];
    const float* rvar  = (const float*)d_in[5];
    const float* cw    = (const float*)d_in[6];
    float* out = (float*)d_out;

    cudaFuncSetAttribute(conv_mma, cudaFuncAttributeMaxDynamicSharedMemorySize, SMEM_DYN);

    wt_prep<<<(NCC * B_FL + 255) / 256, 256>>>(cw);
    bn_relu_tr<<<32 * NCC * 15, 256>>>(x, gamma, beta, rmean, rvar);
    conv_mma<<<dim3(14, 32), 256, SMEM_DYN>>>(out);
    knop<<<1, 32>>>();
}